// round 10
// baseline (speedup 1.0000x reference)
#include <cuda_runtime.h>

// out[b, d] = initial[b, d] * (sum_k X[b,k]*alphas[k]) + X[b,d] + bias[d]
// B = 16384 rows, D = 2048 cols, fp32.
//
// R7 structure (two rows per CTA, 512 threads, single-barrier reduction)
// with occupancy raised to 4 CTAs/SM: 32 regs x 512 thr x 4 CTAs = exactly
// the 64K-register file -> 2048 resident threads (100% occupancy). A 4th
// independent CTA keeps loads issuing while others wait at their barrier.

#define THREADS 512
#define D_DIM 2048
#define D4 (D_DIM / 4)          // 512 float4 per row == THREADS
#define NWARPS (THREADS / 32)   // 16

__global__ __launch_bounds__(THREADS, 4)
void crossnet_kernel(const float* __restrict__ initial,
                     const float* __restrict__ X,
                     const float* __restrict__ alphas,
                     const float* __restrict__ bias,
                     float* __restrict__ out)
{
    const int t = threadIdx.x;
    const int lane = t & 31;
    const int wid = t >> 5;

    const size_t base0 = (size_t)(2 * blockIdx.x) * D4;
    const size_t base1 = base0 + D4;

    const float4* __restrict__ X4 = reinterpret_cast<const float4*>(X);
    const float4* __restrict__ I4 = reinterpret_cast<const float4*>(initial);
    const float4* __restrict__ A4 = reinterpret_cast<const float4*>(alphas);
    const float4* __restrict__ B4 = reinterpret_cast<const float4*>(bias);
    float4* __restrict__ O4 = reinterpret_cast<float4*>(out);

    // Front-batched loads: 4 streaming LDG.128 + 2 cached (alphas/bias hot).
    float4 x0 = __ldcs(&X4[base0 + t]);
    float4 x1 = __ldcs(&X4[base1 + t]);
    float4 i0 = __ldcs(&I4[base0 + t]);
    float4 i1 = __ldcs(&I4[base1 + t]);
    float4 a  = A4[t];
    float4 b  = B4[t];

    // Per-thread partial dot products for both rows.
    float dot0 = x0.x * a.x + x0.y * a.y + x0.z * a.z + x0.w * a.w;
    float dot1 = x1.x * a.x + x1.y * a.y + x1.z * a.z + x1.w * a.w;

    // Warp reduce both rows.
    #pragma unroll
    for (int off = 16; off > 0; off >>= 1) {
        dot0 += __shfl_xor_sync(0xFFFFFFFFu, dot0, off);
        dot1 += __shfl_xor_sync(0xFFFFFFFFu, dot1, off);
    }

    // Single-barrier block reduce over 16 warps; every warp folds the
    // partials redundantly via shuffle (no second barrier).
    __shared__ float ws0[NWARPS];
    __shared__ float ws1[NWARPS];
    if (lane == 0) { ws0[wid] = dot0; ws1[wid] = dot1; }
    __syncthreads();

    float s0 = (lane < NWARPS) ? ws0[lane] : 0.0f;
    float s1 = (lane < NWARPS) ? ws1[lane] : 0.0f;
    #pragma unroll
    for (int off = NWARPS / 2; off > 0; off >>= 1) {
        s0 += __shfl_xor_sync(0xFFFFFFFFu, s0, off);
        s1 += __shfl_xor_sync(0xFFFFFFFFu, s1, off);
    }
    const float scale0 = __shfl_sync(0xFFFFFFFFu, s0, 0);
    const float scale1 = __shfl_sync(0xFFFFFFFFu, s1, 0);

    float4 o;
    o.x = fmaf(i0.x, scale0, x0.x + b.x);
    o.y = fmaf(i0.y, scale0, x0.y + b.y);
    o.z = fmaf(i0.z, scale0, x0.z + b.z);
    o.w = fmaf(i0.w, scale0, x0.w + b.w);
    __stcs(&O4[base0 + t], o);

    o.x = fmaf(i1.x, scale1, x1.x + b.x);
    o.y = fmaf(i1.y, scale1, x1.y + b.y);
    o.z = fmaf(i1.z, scale1, x1.z + b.z);
    o.w = fmaf(i1.w, scale1, x1.w + b.w);
    __stcs(&O4[base1 + t], o);
}

extern "C" void kernel_launch(void* const* d_in, const int* in_sizes, int n_in,
                              void* d_out, int out_size)
{
    const float* initial = (const float*)d_in[0];
    const float* X       = (const float*)d_in[1];
    const float* alphas  = (const float*)d_in[2];
    const float* bias    = (const float*)d_in[3];
    float* out           = (float*)d_out;

    const int B = in_sizes[0] / D_DIM;   // 16384
    crossnet_kernel<<<B / 2, THREADS>>>(initial, X, alphas, bias, out);
}

// round 11
// speedup vs baseline: 1.0036x; 1.0036x over previous
#include <cuda_runtime.h>

// out[b, d] = initial[b, d] * (sum_k X[b,k]*alphas[k]) + X[b,d] + bias[d]
// B = 16384 rows, D = 2048 cols, fp32.
//
// FINAL (R7/R9 optimum): TWO rows per CTA, 512 threads, 3 CTAs/SM.
// Each thread covers exactly 1 float4 per row per array (32 regs); one
// barrier + one smem round-trip serves both row reductions. Single-pass:
// X stays in registers for both the dot product and the epilogue, so DRAM
// traffic is the 384 MB algorithmic minimum. The bound-3 register slack
// (16K regs free) keeps CTA rotation smooth -- bound-4 (full RF) measured
// 2% slower. Measured: 54.1-54.4 us kernel, 83-84% DRAM-active, 6.6 TB/s.

#define THREADS 512
#define D_DIM 2048
#define D4 (D_DIM / 4)          // 512 float4 per row == THREADS
#define NWARPS (THREADS / 32)   // 16

__global__ __launch_bounds__(THREADS, 3)
void crossnet_kernel(const float* __restrict__ initial,
                     const float* __restrict__ X,
                     const float* __restrict__ alphas,
                     const float* __restrict__ bias,
                     float* __restrict__ out)
{
    const int t = threadIdx.x;
    const int lane = t & 31;
    const int wid = t >> 5;

    const size_t base0 = (size_t)(2 * blockIdx.x) * D4;
    const size_t base1 = base0 + D4;

    const float4* __restrict__ X4 = reinterpret_cast<const float4*>(X);
    const float4* __restrict__ I4 = reinterpret_cast<const float4*>(initial);
    const float4* __restrict__ A4 = reinterpret_cast<const float4*>(alphas);
    const float4* __restrict__ B4 = reinterpret_cast<const float4*>(bias);
    float4* __restrict__ O4 = reinterpret_cast<float4*>(out);

    // Front-batched loads: 4 streaming LDG.128 + 2 cached (alphas/bias hot).
    float4 x0 = __ldcs(&X4[base0 + t]);
    float4 x1 = __ldcs(&X4[base1 + t]);
    float4 i0 = __ldcs(&I4[base0 + t]);
    float4 i1 = __ldcs(&I4[base1 + t]);
    float4 a  = A4[t];
    float4 b  = B4[t];

    // Per-thread partial dot products for both rows.
    float dot0 = x0.x * a.x + x0.y * a.y + x0.z * a.z + x0.w * a.w;
    float dot1 = x1.x * a.x + x1.y * a.y + x1.z * a.z + x1.w * a.w;

    // Warp reduce both rows.
    #pragma unroll
    for (int off = 16; off > 0; off >>= 1) {
        dot0 += __shfl_xor_sync(0xFFFFFFFFu, dot0, off);
        dot1 += __shfl_xor_sync(0xFFFFFFFFu, dot1, off);
    }

    // Single-barrier block reduce over 16 warps; every warp folds the
    // partials redundantly via shuffle (no second barrier).
    __shared__ float ws0[NWARPS];
    __shared__ float ws1[NWARPS];
    if (lane == 0) { ws0[wid] = dot0; ws1[wid] = dot1; }
    __syncthreads();

    float s0 = (lane < NWARPS) ? ws0[lane] : 0.0f;
    float s1 = (lane < NWARPS) ? ws1[lane] : 0.0f;
    #pragma unroll
    for (int off = NWARPS / 2; off > 0; off >>= 1) {
        s0 += __shfl_xor_sync(0xFFFFFFFFu, s0, off);
        s1 += __shfl_xor_sync(0xFFFFFFFFu, s1, off);
    }
    const float scale0 = __shfl_sync(0xFFFFFFFFu, s0, 0);
    const float scale1 = __shfl_sync(0xFFFFFFFFu, s1, 0);

    float4 o;
    o.x = fmaf(i0.x, scale0, x0.x + b.x);
    o.y = fmaf(i0.y, scale0, x0.y + b.y);
    o.z = fmaf(i0.z, scale0, x0.z + b.z);
    o.w = fmaf(i0.w, scale0, x0.w + b.w);
    __stcs(&O4[base0 + t], o);

    o.x = fmaf(i1.x, scale1, x1.x + b.x);
    o.y = fmaf(i1.y, scale1, x1.y + b.y);
    o.z = fmaf(i1.z, scale1, x1.z + b.z);
    o.w = fmaf(i1.w, scale1, x1.w + b.w);
    __stcs(&O4[base1 + t], o);
}

extern "C" void kernel_launch(void* const* d_in, const int* in_sizes, int n_in,
                              void* d_out, int out_size)
{
    const float* initial = (const float*)d_in[0];
    const float* X       = (const float*)d_in[1];
    const float* alphas  = (const float*)d_in[2];
    const float* bias    = (const float*)d_in[3];
    float* out           = (float*)d_out;

    const int B = in_sizes[0] / D_DIM;   // 16384
    crossnet_kernel<<<B / 2, THREADS>>>(initial, X, alphas, bias, out);
}

// round 12
// speedup vs baseline: 1.0104x; 1.0068x over previous
#include <cuda_runtime.h>

// out[b, d] = initial[b, d] * (sum_k X[b,k]*alphas[k]) + X[b,d] + bias[d]
// B = 16384 rows, D = 2048 cols, fp32.
//
// FINAL: TWO rows per CTA, 512 threads, 3 CTAs/SM (bound-3 leaves 16K-reg
// slack for smooth CTA rotation; bound-4 measured 2% slower). Each thread
// covers exactly 1 float4 per row per array (32 regs). One barrier + one
// smem round-trip serves both row reductions. Single-pass: X stays in
// registers for both the dot product and the epilogue -> DRAM traffic is
// the 384 MB algorithmic minimum.
// Measured best: 53.66 us kernel, 84.3% DRAM-active, 6.68 TB/s.

#define THREADS 512
#define D_DIM 2048
#define D4 (D_DIM / 4)          // 512 float4 per row == THREADS
#define NWARPS (THREADS / 32)   // 16

__global__ __launch_bounds__(THREADS, 3)
void crossnet_kernel(const float* __restrict__ initial,
                     const float* __restrict__ X,
                     const float* __restrict__ alphas,
                     const float* __restrict__ bias,
                     float* __restrict__ out)
{
    const int t = threadIdx.x;
    const int lane = t & 31;
    const int wid = t >> 5;

    const size_t base0 = (size_t)(2 * blockIdx.x) * D4;
    const size_t base1 = base0 + D4;

    const float4* __restrict__ X4 = reinterpret_cast<const float4*>(X);
    const float4* __restrict__ I4 = reinterpret_cast<const float4*>(initial);
    const float4* __restrict__ A4 = reinterpret_cast<const float4*>(alphas);
    const float4* __restrict__ B4 = reinterpret_cast<const float4*>(bias);
    float4* __restrict__ O4 = reinterpret_cast<float4*>(out);

    // Front-batched loads: 4 streaming LDG.128 + 2 cached (alphas/bias hot).
    float4 x0 = __ldcs(&X4[base0 + t]);
    float4 x1 = __ldcs(&X4[base1 + t]);
    float4 i0 = __ldcs(&I4[base0 + t]);
    float4 i1 = __ldcs(&I4[base1 + t]);
    float4 a  = A4[t];
    float4 b  = B4[t];

    // Per-thread partial dot products for both rows.
    float dot0 = x0.x * a.x + x0.y * a.y + x0.z * a.z + x0.w * a.w;
    float dot1 = x1.x * a.x + x1.y * a.y + x1.z * a.z + x1.w * a.w;

    // Warp reduce both rows.
    #pragma unroll
    for (int off = 16; off > 0; off >>= 1) {
        dot0 += __shfl_xor_sync(0xFFFFFFFFu, dot0, off);
        dot1 += __shfl_xor_sync(0xFFFFFFFFu, dot1, off);
    }

    // Single-barrier block reduce over 16 warps; every warp folds the
    // partials redundantly via shuffle (no second barrier).
    __shared__ float ws0[NWARPS];
    __shared__ float ws1[NWARPS];
    if (lane == 0) { ws0[wid] = dot0; ws1[wid] = dot1; }
    __syncthreads();

    float s0 = (lane < NWARPS) ? ws0[lane] : 0.0f;
    float s1 = (lane < NWARPS) ? ws1[lane] : 0.0f;
    #pragma unroll
    for (int off = NWARPS / 2; off > 0; off >>= 1) {
        s0 += __shfl_xor_sync(0xFFFFFFFFu, s0, off);
        s1 += __shfl_xor_sync(0xFFFFFFFFu, s1, off);
    }
    const float scale0 = __shfl_sync(0xFFFFFFFFu, s0, 0);
    const float scale1 = __shfl_sync(0xFFFFFFFFu, s1, 0);

    float4 o;
    o.x = fmaf(i0.x, scale0, x0.x + b.x);
    o.y = fmaf(i0.y, scale0, x0.y + b.y);
    o.z = fmaf(i0.z, scale0, x0.z + b.z);
    o.w = fmaf(i0.w, scale0, x0.w + b.w);
    __stcs(&O4[base0 + t], o);

    o.x = fmaf(i1.x, scale1, x1.x + b.x);
    o.y = fmaf(i1.y, scale1, x1.y + b.y);
    o.z = fmaf(i1.z, scale1, x1.z + b.z);
    o.w = fmaf(i1.w, scale1, x1.w + b.w);
    __stcs(&O4[base1 + t], o);
}

extern "C" void kernel_launch(void* const* d_in, const int* in_sizes, int n_in,
                              void* d_out, int out_size)
{
    const float* initial = (const float*)d_in[0];
    const float* X       = (const float*)d_in[1];
    const float* alphas  = (const float*)d_in[2];
    const float* bias    = (const float*)d_in[3];
    float* out           = (float*)d_out;

    const int B = in_sizes[0] / D_DIM;   // 16384
    crossnet_kernel<<<B / 2, THREADS>>>(initial, X, alphas, bias, out);
}